// round 16
// baseline (speedup 1.0000x reference)
#include <cuda_runtime.h>
#include <cuda_bf16.h>
#include <cstdint>
#include <algorithm>

// ---------------------------------------------------------------------------
// UniformNeighborSampler:
//   out[r, j] = (float) adj[g_id, ids[r], sel[j]],  g_id=1, ins=1 (adj_ins)
//   sel = jax.random.permutation(jax.random.key(42), 128)[:32]
//     (partitionable threefry, verified exact since R4)
//
// R16: the wall (8.6us across 9 kernel shapes) is random-granule DRAM
// efficiency (~30% of peak for ~40k random 512B rows). Change the ORDER:
//   K1 (bin):   bucket rows by ids[r]>>5 (16KB node windows) via atomics
//               into static device scratch.
//   K2 (gather): one warp per bucket in ascending node order -> adjacency
//               reads become an ascending DRAM-page sweep; duplicates are
//               temporally adjacent (L2 hits). Counters re-zeroed in K2 so
//               every graph replay works. Overflow list keeps correctness
//               for any input skew.
// ---------------------------------------------------------------------------

namespace {

constexpr int N_GRAPHS = 4;
constexpr int DEGREES  = 128;
constexpr int SAMPLES  = 32;
constexpr int G_ID     = 1;

constexpr int BUCKET_SHIFT = 5;            // 32 nodes per bucket (16KB window)
constexpr int NBUCK        = 8192;         // covers id < 262144 (need 3125)
constexpr int CAP          = 64;           // slots per bucket (mean fill ~16)
constexpr int OVCAP        = 8192;

struct Sel32 { int s[SAMPLES]; };

static inline uint32_t rotl32(uint32_t x, int d) {
    return (x << d) | (x >> (32 - d));
}

static void threefry2x32(uint32_t k0, uint32_t k1,
                         uint32_t c0, uint32_t c1,
                         uint32_t* o0, uint32_t* o1) {
    uint32_t ks[3] = {k0, k1, k0 ^ k1 ^ 0x1BD11BDAu};
    uint32_t x0 = c0 + ks[0];
    uint32_t x1 = c1 + ks[1];
    static const int rot[2][4] = {{13, 15, 26, 6}, {17, 29, 16, 24}};
    for (int i = 0; i < 5; i++) {
        const int* r = rot[i & 1];
        for (int j = 0; j < 4; j++) {
            x0 += x1;
            x1 = rotl32(x1, r[j]);
            x1 ^= x0;
        }
        x0 += ks[(i + 1) % 3];
        x1 += ks[(i + 2) % 3] + (uint32_t)(i + 1);
    }
    *o0 = x0;
    *o1 = x1;
}

static void compute_sel(Sel32* sel) {
    const uint32_t k0 = 0u, k1 = 42u;          // jax.random.key(42)

    uint32_t sk0, sk1;                          // partitionable split
    threefry2x32(k0, k1, 0u, 1u, &sk0, &sk1);

    uint32_t bits[DEGREES];                     // counter-mode bits, xor-fold
    for (int i = 0; i < DEGREES; i++) {
        uint32_t y0, y1;
        threefry2x32(sk0, sk1, 0u, (uint32_t)i, &y0, &y1);
        bits[i] = y0 ^ y1;
    }

    uint64_t kv[DEGREES];
    for (int i = 0; i < DEGREES; i++)
        kv[i] = ((uint64_t)bits[i] << 32) | (uint32_t)i;
    std::sort(kv, kv + DEGREES);

    for (int j = 0; j < SAMPLES; j++)
        sel->s[j] = (int)(kv[j] & 0xFFFFFFFFu);
}

} // namespace

// Static scratch (allocation-free; zero-initialized at module load; K2
// re-zeroes counters after use so graph replays stay consistent).
__device__ int  g_count[NBUCK];
__device__ int2 g_slots[NBUCK * CAP];       // .x = output row r, .y = node id
__device__ int  g_ovcount;
__device__ int  g_ovlist[OVCAP];

// K1: bin rows by node-id window.
__global__ __launch_bounds__(256)
void bin_kernel(const int* __restrict__ ids, int batch)
{
    int r = blockIdx.x * blockDim.x + threadIdx.x;
    if (r >= batch) return;
    int id  = __ldg(&ids[r]);
    int b   = id >> BUCKET_SHIFT;
    int pos = atomicAdd(&g_count[b], 1);
    if (pos < CAP) {
        g_slots[b * CAP + pos] = make_int2(r, id);
    } else {
        int p = atomicAdd(&g_ovcount, 1);
        if (p < OVCAP) g_ovlist[p] = r;
    }
}

// K2: one warp per bucket, ascending node order => DRAM page sweep.
__global__ __launch_bounds__(256)
void gather_kernel(const int* __restrict__ adj_g,
                   const int* __restrict__ ids,
                   float* __restrict__ out,
                   int nbuckets, Sel32 sel)
{
    const int lane = threadIdx.x & 31;
    const int w    = (int)((blockIdx.x * blockDim.x + threadIdx.x) >> 5);
    const int col  = sel.s[lane];

    if (w < nbuckets) {
        int c = g_count[w];
        if (c > CAP) c = CAP;

        // Preload up to 64 entries into registers (coalesced int2 loads).
        int2 eA = make_int2(0, 0), eB = make_int2(0, 0);
        if (lane < c)      eA = g_slots[w * CAP + lane];
        if (32 + lane < c) eB = g_slots[w * CAP + 32 + lane];

        // Process entries in MLP=8 batches; ids within a bucket span one
        // 16KB window -> page-local reads.
        for (int base = 0; base < c; base += 8) {
            int n = c - base; if (n > 8) n = 8;
            int rr[8], vv[8];
#pragma unroll
            for (int k = 0; k < 8; k++) {
                if (k < n) {
                    int kk  = base + k;              // uniform across warp
                    int2 h  = (kk < 32) ? eA : eB;
                    int src = kk & 31;
                    int er  = __shfl_sync(0xffffffffu, h.x, src);
                    int eid = __shfl_sync(0xffffffffu, h.y, src);
                    rr[k] = er;
                    vv[k] = __ldg(adj_g + (long long)eid * DEGREES + col);
                }
            }
#pragma unroll
            for (int k = 0; k < 8; k++)
                if (k < n)
                    out[(long long)rr[k] * SAMPLES + lane] = (float)vv[k];
        }

        if (lane == 0) g_count[w] = 0;      // reset for next replay
    }

    // Overflow entries (normally zero): warp 0 of block 0 handles directly.
    if (blockIdx.x == 0 && (threadIdx.x >> 5) == 0) {
        int oc = g_ovcount; if (oc > OVCAP) oc = OVCAP;
        for (int i = 0; i < oc; i++) {
            int r  = g_ovlist[i];
            int id = __ldg(&ids[r]);
            int v  = __ldg(adj_g + (long long)id * DEGREES + col);
            out[(long long)r * SAMPLES + lane] = (float)v;
        }
        if (lane == 0) g_ovcount = 0;
    }
}

extern "C" void kernel_launch(void* const* d_in, const int* in_sizes, int n_in,
                              void* d_out, int out_size)
{
    // Locate inputs by SIZE (layout-order independent).
    int adj_idx0 = -1, adj_idx1 = -1, ids_idx = -1;
    for (int i = 0; i < n_in; i++) {
        long long sz = in_sizes[i];
        if (sz > 1000000) {
            if (adj_idx0 < 0) adj_idx0 = i;
            else if (adj_idx1 < 0) adj_idx1 = i;
        } else if (sz > 1) {
            ids_idx = i;
        }
    }
    if (adj_idx0 < 0) adj_idx0 = 0;
    if (adj_idx1 < 0) adj_idx1 = 1;
    if (ids_idx  < 0) ids_idx  = 3;

    const int* adj_ins = (const int*)d_in[adj_idx0];   // ins=1 -> active table
    const int* ids     = (const int*)d_in[ids_idx];

    const int num_nodes = in_sizes[adj_idx0] / (N_GRAPHS * DEGREES);
    const int batch     = in_sizes[ids_idx];           // 50000 rows

    const int* adj_g = adj_ins + (long long)G_ID * num_nodes * DEGREES;

    Sel32 sel;
    compute_sel(&sel);

    // K1: bin
    {
        const int threads = 256;
        const int blocks  = (batch + threads - 1) / threads;   // 196
        bin_kernel<<<blocks, threads>>>(ids, batch);
    }

    // K2: ordered gather
    {
        const int nbuckets = (num_nodes + (1 << BUCKET_SHIFT) - 1) >> BUCKET_SHIFT; // 3125
        const int threads  = 256;                                // 8 warps
        const int blocks   = (nbuckets * 32 + threads - 1) / threads;  // 391
        gather_kernel<<<blocks, threads>>>(adj_g, ids, (float*)d_out, nbuckets, sel);
    }
}